// round 2
// baseline (speedup 1.0000x reference)
#include <cuda_runtime.h>
#include <cuda_bf16.h>

namespace {

constexpr int B = 16, H = 512, W = 512;
constexpr int TX = 32, TY = 8;
constexpr int NCOL = TX + 4;        // 36 columns of sorted-5 per tile row
constexpr int NTHREADS = TX * TY;   // 256

__device__ __forceinline__ int reflect(int i, int n) {
    if (i < 0) i = -i;
    if (i >= n) i = 2 * n - 2 - i;
    return i;
}

// descending compare-exchange: a >= b afterwards
__device__ __forceinline__ void ceD(float& a, float& b) {
    float mx = fmaxf(a, b);
    float mn = fminf(a, b);
    a = mx; b = mn;
}

// greatest power of two strictly less than N (for N >= 2), as a template
// so no host constexpr function is called from device code.
template<int N> struct GP2      { static constexpr int value = 2 * GP2<(N + 1) / 2>::value; };
template<>      struct GP2<2>   { static constexpr int value = 1; };
template<>      struct GP2<1>   { static constexpr int value = 1; };

// Lang's arbitrary-N bitonic merge, descending output.
// Input must be bitonic in mountain form (ascending then descending).
template<int N>
__device__ __forceinline__ void bmergeD(float* v) {
    if constexpr (N > 1) {
        constexpr int K = GP2<N>::value;
        #pragma unroll
        for (int i = 0; i < N - K; i++) ceD(v[i], v[i + K]);
        bmergeD<K>(v);
        bmergeD<N - K>(v + K);
    }
}

// classic optimal 9-CE sorting network for 5 elements (descending)
__device__ __forceinline__ void sort5D(float* a) {
    ceD(a[0], a[1]); ceD(a[3], a[4]); ceD(a[2], a[4]); ceD(a[2], a[3]);
    ceD(a[1], a[4]); ceD(a[0], a[3]); ceD(a[0], a[2]); ceD(a[1], a[3]);
    ceD(a[1], a[2]);
}

__global__ __launch_bounds__(NTHREADS)
void ordfilter_kernel(const float* __restrict__ inp, float* __restrict__ out) {
    // sc[k][cy][cx] = k-th largest of the vertical 5-window at (tile col cx, tile row cy)
    __shared__ float sc[5][TY][NCOL];

    const int b   = blockIdx.z;
    const int x0  = blockIdx.x * TX;
    const int y0  = blockIdx.y * TY;
    const int tid = threadIdx.x;
    const float* __restrict__ img = inp + (size_t)b * H * W;

    // ---- Phase 1: vertical column sorts (shared across 5 horizontal offsets) ----
    #pragma unroll
    for (int idx = tid; idx < NCOL * TY; idx += NTHREADS) {
        const int cx = idx % NCOL;
        const int cy = idx / NCOL;
        const int gx = reflect(x0 + cx - 2, W);
        const int yc = y0 + cy;
        float v[5];
        #pragma unroll
        for (int j = 0; j < 5; j++)
            v[j] = img[(size_t)reflect(yc - 2 + j, H) * W + gx];
        sort5D(v);
        #pragma unroll
        for (int j = 0; j < 5; j++) sc[j][cy][cx] = v[j];
    }
    __syncthreads();

    // ---- Phase 2: per-pixel merge of 5 sorted columns, keep top 9 ----
    const int tx = tid & (TX - 1);
    const int ty = tid / TX;

    float t[10];
    {
        float c0[5], c1[5];
        #pragma unroll
        for (int j = 0; j < 5; j++) { c0[j] = sc[j][ty][tx]; c1[j] = sc[j][ty][tx + 1]; }
        // mountain: reverse(c0) (asc) ++ c1 (desc)
        #pragma unroll
        for (int j = 0; j < 5; j++) t[j] = c0[4 - j];
        #pragma unroll
        for (int j = 0; j < 5; j++) t[5 + j] = c1[j];
        bmergeD<10>(t);   // t[0..8] = top-9 of columns 0,1 (t[9] dead -> DCE)
    }

    #pragma unroll
    for (int c = 2; c < 5; c++) {
        float nc[5];
        #pragma unroll
        for (int j = 0; j < 5; j++) nc[j] = sc[j][ty][tx + c];
        float u[14];
        // mountain: reverse(t[0..8]) (asc) ++ nc (desc)
        #pragma unroll
        for (int j = 0; j < 9; j++) u[j] = t[8 - j];
        #pragma unroll
        for (int j = 0; j < 5; j++) u[9 + j] = nc[j];
        bmergeD<14>(u);   // u[9..13] dead -> CEs feeding only them are DCE'd
        #pragma unroll
        for (int j = 0; j < 9; j++) t[j] = u[j];
    }

    float s = 0.0f;
    #pragma unroll
    for (int j = 0; j < 9; j++) s += t[j];

    out[((size_t)b * H + (y0 + ty)) * W + (x0 + tx)] = s * (1.0f / 9.0f);
}

} // namespace

extern "C" void kernel_launch(void* const* d_in, const int* in_sizes, int n_in,
                              void* d_out, int out_size) {
    const float* inp = (const float*)d_in[0];
    float* out = (float*)d_out;
    dim3 grid(W / TX, H / TY, B);   // 16 x 64 x 16
    ordfilter_kernel<<<grid, NTHREADS>>>(inp, out);
}

// round 4
// speedup vs baseline: 1.5266x; 1.5266x over previous
#include <cuda_runtime.h>
#include <cuda_fp16.h>
#include <cuda_bf16.h>

namespace {

constexpr int B = 16, H = 512, W = 512;
constexpr int TPX = 32;              // pixel-pair lanes per row (each thread: pixels tx and tx+32)
constexpr int TY  = 8;               // tile rows
constexpr int TILE_W = 64;           // tile width in pixels
constexpr int NPACK = TPX + 4;       // 36 packed sorted-columns per tile row
constexpr int NTHREADS = TPX * TY;   // 256

__device__ __forceinline__ int reflect(int i, int n) {
    if (i < 0) i = -i;
    if (i >= n) i = 2 * n - 2 - i;
    return i;
}

// packed descending compare-exchange on 2 independent lanes: a >= b per lane
__device__ __forceinline__ void ceD(__half2& a, __half2& b) {
    __half2 mx = __hmax2(a, b);
    __half2 mn = __hmin2(a, b);
    a = mx; b = mn;
}

// greatest power of two strictly less than N (N >= 2)
template<int N> struct GP2    { static constexpr int value = 2 * GP2<(N + 1) / 2>::value; };
template<>      struct GP2<2> { static constexpr int value = 1; };
template<>      struct GP2<1> { static constexpr int value = 1; };

// Lang's arbitrary-N bitonic merge, descending output.
// Input must be bitonic in mountain form (ascending then descending).
template<int N>
__device__ __forceinline__ void bmergeD(__half2* v) {
    if constexpr (N > 1) {
        constexpr int K = GP2<N>::value;
        #pragma unroll
        for (int i = 0; i < N - K; i++) ceD(v[i], v[i + K]);
        bmergeD<K>(v);
        bmergeD<N - K>(v + K);
    }
}

// optimal 9-CE sorting network for 5 elements (descending), packed
__device__ __forceinline__ void sort5D(__half2* a) {
    ceD(a[0], a[1]); ceD(a[3], a[4]); ceD(a[2], a[4]); ceD(a[2], a[3]);
    ceD(a[1], a[4]); ceD(a[0], a[3]); ceD(a[0], a[2]); ceD(a[1], a[3]);
    ceD(a[1], a[2]);
}

__global__ __launch_bounds__(NTHREADS)
void ordfilter_kernel(const float* __restrict__ inp, float* __restrict__ out) {
    // sc[j][cy][p] : j-th largest of the vertical 5-window, packed half2:
    //   lane .x = image column x0 + p - 2        (left-half pixel's window col)
    //   lane .y = image column x0 + 32 + p - 2   (right-half pixel's window col)
    __shared__ __half2 sc[5][TY][NPACK];

    const int b   = blockIdx.z;
    const int x0  = blockIdx.x * TILE_W;
    const int y0  = blockIdx.y * TY;
    const int tx  = threadIdx.x;           // 0..31
    const int ty  = threadIdx.y;           // 0..7
    const int tid = ty * TPX + tx;
    const float* __restrict__ img = inp + (size_t)b * H * W;

    // ---- Phase 1: packed vertical column sorts ----
    #pragma unroll
    for (int task = tid; task < NPACK * TY; task += NTHREADS) {
        const int p  = task % NPACK;
        const int cy = task / NPACK;
        const int gxL = reflect(x0 + p - 2, W);
        const int gxR = reflect(x0 + TPX + p - 2, W);
        __half2 v[5];
        #pragma unroll
        for (int j = 0; j < 5; j++) {
            const int yy = reflect(y0 + cy - 2 + j, H);
            const float* row = img + (size_t)yy * W;
            v[j] = __floats2half2_rn(row[gxL], row[gxR]);
        }
        sort5D(v);
        #pragma unroll
        for (int j = 0; j < 5; j++) sc[j][cy][p] = v[j];
    }
    __syncthreads();

    // ---- Phase 2: per pixel-pair merge of 5 sorted columns, keep top 9 ----
    __half2 t[10];
    {
        __half2 c0[5], c1[5];
        #pragma unroll
        for (int j = 0; j < 5; j++) { c0[j] = sc[j][ty][tx]; c1[j] = sc[j][ty][tx + 1]; }
        // mountain: reverse(c0) (asc) ++ c1 (desc)
        #pragma unroll
        for (int j = 0; j < 5; j++) t[j] = c0[4 - j];
        #pragma unroll
        for (int j = 0; j < 5; j++) t[5 + j] = c1[j];
        bmergeD<10>(t);   // t[0..8] = top-9 of columns 0,1 (t[9] dead -> DCE)
    }

    #pragma unroll
    for (int c = 2; c < 5; c++) {
        __half2 nc[5];
        #pragma unroll
        for (int j = 0; j < 5; j++) nc[j] = sc[j][ty][tx + c];
        __half2 u[14];
        // mountain: reverse(t[0..8]) (asc) ++ nc (desc)
        #pragma unroll
        for (int j = 0; j < 9; j++) u[j] = t[8 - j];
        #pragma unroll
        for (int j = 0; j < 5; j++) u[9 + j] = nc[j];
        bmergeD<14>(u);   // u[9..13] dead -> CEs feeding only them are DCE'd
        #pragma unroll
        for (int j = 0; j < 9; j++) t[j] = u[j];
    }

    // Sum the 9 survivors in fp32 (fp16 summation would cost ~2e-3 rel err)
    float sx = 0.0f, sy = 0.0f;
    #pragma unroll
    for (int j = 0; j < 9; j++) {
        const float2 f = __half22float2(t[j]);
        sx += f.x; sy += f.y;
    }

    float* orow = out + ((size_t)b * H + (y0 + ty)) * W + x0;
    orow[tx]       = sx * (1.0f / 9.0f);
    orow[tx + TPX] = sy * (1.0f / 9.0f);
}

} // namespace

extern "C" void kernel_launch(void* const* d_in, const int* in_sizes, int n_in,
                              void* d_out, int out_size) {
    const float* inp = (const float*)d_in[0];
    float* out = (float*)d_out;
    dim3 grid(W / TILE_W, H / TY, B);   // 8 x 64 x 16
    dim3 block(TPX, TY);                // 32 x 8
    ordfilter_kernel<<<grid, block>>>(inp, out);
}

// round 5
// speedup vs baseline: 1.9499x; 1.2773x over previous
#include <cuda_runtime.h>
#include <cuda_fp16.h>
#include <cuda_bf16.h>

namespace {

constexpr int B = 16, H = 512, W = 512;
constexpr int TPX   = 16;            // threads in x; each handles packed pixels 2tx, 2tx+1
constexpr int TY    = 16;            // tile rows
constexpr int TILE_W = 64;           // tile width in pixels (halves packed 32 apart)
constexpr int NPACK = 36;            // packed columns incl. halo (32 + 4)
constexpr int NTHREADS = TPX * TY;   // 256

__device__ __forceinline__ int reflect(int i, int n) {
    if (i < 0) i = -i;
    if (i >= n) i = 2 * n - 2 - i;
    return i;
}

// packed descending compare-exchange on 2 independent lanes: a >= b per lane
__device__ __forceinline__ void ceD(__half2& a, __half2& b) {
    __half2 mx = __hmax2(a, b);
    __half2 mn = __hmin2(a, b);
    a = mx; b = mn;
}

// greatest power of two strictly less than N (N >= 2)
template<int N> struct GP2    { static constexpr int value = 2 * GP2<(N + 1) / 2>::value; };
template<>      struct GP2<2> { static constexpr int value = 1; };
template<>      struct GP2<1> { static constexpr int value = 1; };

// Lang's arbitrary-N bitonic merge, descending output. Input bitonic (mountain).
template<int N>
__device__ __forceinline__ void bmergeD(__half2* v) {
    if constexpr (N > 1) {
        constexpr int K = GP2<N>::value;
        #pragma unroll
        for (int i = 0; i < N - K; i++) ceD(v[i], v[i + K]);
        bmergeD<K>(v);
        bmergeD<N - K>(v + K);
    }
}

// optimal 9-CE sorting network for 5 elements (descending), packed
__device__ __forceinline__ void sort5D(__half2* a) {
    ceD(a[0], a[1]); ceD(a[3], a[4]); ceD(a[2], a[4]); ceD(a[2], a[3]);
    ceD(a[1], a[4]); ceD(a[0], a[3]); ceD(a[0], a[2]); ceD(a[1], a[3]);
    ceD(a[1], a[2]);
}

// merge two sorted-desc-5 lists into sorted-desc-10 (full, 15 CE)
__device__ __forceinline__ void merge55(const __half2* a, const __half2* b, __half2* out10) {
    #pragma unroll
    for (int j = 0; j < 5; j++) out10[j] = a[4 - j];   // ascending
    #pragma unroll
    for (int j = 0; j < 5; j++) out10[5 + j] = b[j];   // descending
    bmergeD<10>(out10);
}

// merge sorted-desc-9 with sorted-desc-5, return top-9 (pruned bitonic-14)
__device__ __forceinline__ void merge95_top9(const __half2* m9, const __half2* c5, __half2* out9) {
    __half2 w[14];
    #pragma unroll
    for (int j = 0; j < 9; j++) w[j] = m9[8 - j];      // ascending
    #pragma unroll
    for (int j = 0; j < 5; j++) w[9 + j] = c5[j];      // descending
    bmergeD<14>(w);                                    // w[9..13] dead -> DCE
    #pragma unroll
    for (int j = 0; j < 9; j++) out9[j] = w[j];
}

__global__ __launch_bounds__(NTHREADS)
void ordfilter_kernel(const float* __restrict__ inp, float* __restrict__ out) {
    // sc[j][cy][p] : j-th largest of the vertical 5-window at packed column p
    //   lane .x = image column x0 + p - 2
    //   lane .y = image column x0 + 32 + p - 2
    __shared__ __half2 sc[5][TY][NPACK];

    const int b   = blockIdx.z;
    const int x0  = blockIdx.x * TILE_W;
    const int y0  = blockIdx.y * TY;
    const int tx  = threadIdx.x;           // 0..15
    const int ty  = threadIdx.y;           // 0..15
    const int tid = ty * TPX + tx;
    const float* __restrict__ img = inp + (size_t)b * H * W;

    // ---- Phase 1: packed vertical column sorts ----
    for (int task = tid; task < NPACK * TY; task += NTHREADS) {
        const int p  = task % NPACK;
        const int cy = task / NPACK;
        const int gxL = reflect(x0 + p - 2, W);
        const int gxR = reflect(x0 + 32 + p - 2, W);
        __half2 v[5];
        #pragma unroll
        for (int j = 0; j < 5; j++) {
            const int yy = reflect(y0 + cy - 2 + j, H);
            const float* row = img + (size_t)yy * W;
            v[j] = __floats2half2_rn(row[gxL], row[gxR]);
        }
        sort5D(v);
        #pragma unroll
        for (int j = 0; j < 5; j++) sc[j][cy][p] = v[j];
    }
    __syncthreads();

    // ---- Phase 2: two adjacent packed pixels per thread, sharing 4 columns ----
    // pixel0 = packed col 2tx,   window p in [2tx   .. 2tx+4]
    // pixel1 = packed col 2tx+1, window p in [2tx+1 .. 2tx+5]
    // shared columns: p = 2tx+1 .. 2tx+4
    const int p0 = 2 * tx;

    // load 6 columns as LDS.64 pairs (p0 even -> 8B aligned)
    __half2 col[6][5];
    #pragma unroll
    for (int j = 0; j < 5; j++) {
        #pragma unroll
        for (int c = 0; c < 6; c += 2) {
            const float2 r = *reinterpret_cast<const float2*>(&sc[j][ty][p0 + c]);
            col[c][j]     = *reinterpret_cast<const __half2*>(&r.x);
            col[c + 1][j] = *reinterpret_cast<const __half2*>(&r.y);
        }
    }

    // shared top-9 of the 4 middle columns
    __half2 A10[10], B10[10];
    merge55(col[1], col[2], A10);
    merge55(col[3], col[4], B10);

    __half2 u[20];
    #pragma unroll
    for (int j = 0; j < 10; j++) u[j] = A10[9 - j];    // ascending
    #pragma unroll
    for (int j = 0; j < 10; j++) u[10 + j] = B10[j];   // descending
    bmergeD<20>(u);                                    // u[9..19] dead -> DCE

    // per-pixel final merges with the private edge columns
    __half2 r0[9], r1[9];
    merge95_top9(u, col[0], r0);
    merge95_top9(u, col[5], r1);

    // fp32 sums (fp16 summation would cost ~1e-3 rel err)
    float s0x = 0.f, s0y = 0.f, s1x = 0.f, s1y = 0.f;
    #pragma unroll
    for (int j = 0; j < 9; j++) {
        const float2 f0 = __half22float2(r0[j]);
        const float2 f1 = __half22float2(r1[j]);
        s0x += f0.x; s0y += f0.y;
        s1x += f1.x; s1y += f1.y;
    }

    float* orow = out + ((size_t)b * H + (y0 + ty)) * W + x0;
    orow[p0]          = s0x * (1.0f / 9.0f);
    orow[p0 + 1]      = s1x * (1.0f / 9.0f);
    orow[p0 + 32]     = s0y * (1.0f / 9.0f);
    orow[p0 + 33]     = s1y * (1.0f / 9.0f);
}

} // namespace

extern "C" void kernel_launch(void* const* d_in, const int* in_sizes, int n_in,
                              void* d_out, int out_size) {
    const float* inp = (const float*)d_in[0];
    float* out = (float*)d_out;
    dim3 grid(W / TILE_W, H / TY, B);   // 8 x 32 x 16
    dim3 block(TPX, TY);                // 16 x 16
    ordfilter_kernel<<<grid, block>>>(inp, out);
}

// round 7
// speedup vs baseline: 2.0649x; 1.0590x over previous
#include <cuda_runtime.h>
#include <cuda_fp16.h>
#include <cuda_bf16.h>

namespace {

constexpr int B = 16, H = 512, W = 512;
constexpr int TPX    = 16;            // threads in x; each handles packed pixels 2tx, 2tx+1
constexpr int TYB    = 16;            // threads in y
constexpr int TILE_W = 64;            // tile width in pixels (halves packed 32 apart)
constexpr int TILE_H = 32;            // tile height: each thread does rows ty and ty+16
constexpr int NPACK  = 36;            // packed columns incl. halo (32 + 4)
constexpr int NTHREADS = TPX * TYB;   // 256
constexpr int NTASKS = NPACK * TILE_H; // 1152 column-sort tasks per block

__device__ __forceinline__ int reflect(int i, int n) {
    if (i < 0) i = -i;
    if (i >= n) i = 2 * n - 2 - i;
    return i;
}

// packed descending compare-exchange on 2 independent lanes: a >= b per lane
__device__ __forceinline__ void ceD(__half2& a, __half2& b) {
    __half2 mx = __hmax2(a, b);
    __half2 mn = __hmin2(a, b);
    a = mx; b = mn;
}

// greatest power of two strictly less than N (N >= 2)
template<int N> struct GP2    { static constexpr int value = 2 * GP2<(N + 1) / 2>::value; };
template<>      struct GP2<2> { static constexpr int value = 1; };
template<>      struct GP2<1> { static constexpr int value = 1; };

// Lang's arbitrary-N bitonic merge, descending output. Input bitonic (mountain).
template<int N>
__device__ __forceinline__ void bmergeD(__half2* v) {
    if constexpr (N > 1) {
        constexpr int K = GP2<N>::value;
        #pragma unroll
        for (int i = 0; i < N - K; i++) ceD(v[i], v[i + K]);
        bmergeD<K>(v);
        bmergeD<N - K>(v + K);
    }
}

// optimal 9-CE sorting network for 5 elements (descending), packed
__device__ __forceinline__ void sort5D(__half2* a) {
    ceD(a[0], a[1]); ceD(a[3], a[4]); ceD(a[2], a[4]); ceD(a[2], a[3]);
    ceD(a[1], a[4]); ceD(a[0], a[3]); ceD(a[0], a[2]); ceD(a[1], a[3]);
    ceD(a[1], a[2]);
}

// merge two sorted-desc-5 lists into sorted-desc-10 (15 CE)
__device__ __forceinline__ void merge55(const __half2* a, const __half2* b, __half2* out10) {
    #pragma unroll
    for (int j = 0; j < 5; j++) out10[j] = a[4 - j];   // ascending
    #pragma unroll
    for (int j = 0; j < 5; j++) out10[5 + j] = b[j];   // descending
    bmergeD<10>(out10);
}

// merge sorted-desc-9 with sorted-desc-5, return top-9 (pruned bitonic-14)
__device__ __forceinline__ void merge95_top9(const __half2* m9, const __half2* c5, __half2* out9) {
    __half2 w[14];
    #pragma unroll
    for (int j = 0; j < 9; j++) w[j] = m9[8 - j];      // ascending
    #pragma unroll
    for (int j = 0; j < 5; j++) w[9 + j] = c5[j];      // descending
    bmergeD<14>(w);                                    // w[9..13] dead -> DCE
    #pragma unroll
    for (int j = 0; j < 9; j++) out9[j] = w[j];
}

using ScTile = __half2[5][TILE_H][NPACK];

// One pixel-pair-unit: two adjacent packed pixels (4 real pixels) at tile row cy.
__device__ __forceinline__ void phase2_unit(const ScTile& sc, int cy, int tx,
                                            float* __restrict__ orow) {
    const int p0 = 2 * tx;

    // load 6 sorted columns as LDS.64 pairs (p0 even -> 8B aligned)
    __half2 col[6][5];
    #pragma unroll
    for (int j = 0; j < 5; j++) {
        #pragma unroll
        for (int c = 0; c < 6; c += 2) {
            const float2 r = *reinterpret_cast<const float2*>(&sc[j][cy][p0 + c]);
            col[c][j]     = *reinterpret_cast<const __half2*>(&r.x);
            col[c + 1][j] = *reinterpret_cast<const __half2*>(&r.y);
        }
    }

    // shared top-9 of the 4 middle columns
    __half2 A10[10], B10[10];
    merge55(col[1], col[2], A10);
    merge55(col[3], col[4], B10);

    __half2 u[20];
    #pragma unroll
    for (int j = 0; j < 10; j++) u[j] = A10[9 - j];    // ascending
    #pragma unroll
    for (int j = 0; j < 10; j++) u[10 + j] = B10[j];   // descending
    bmergeD<20>(u);                                    // u[9..19] dead -> DCE

    // per-pixel final merges with the private edge columns
    __half2 r0[9], r1[9];
    merge95_top9(u, col[0], r0);
    merge95_top9(u, col[5], r1);

    // fp32 sums
    float s0x = 0.f, s0y = 0.f, s1x = 0.f, s1y = 0.f;
    #pragma unroll
    for (int j = 0; j < 9; j++) {
        const float2 f0 = __half22float2(r0[j]);
        const float2 f1 = __half22float2(r1[j]);
        s0x += f0.x; s0y += f0.y;
        s1x += f1.x; s1y += f1.y;
    }

    orow[p0]      = s0x * (1.0f / 9.0f);
    orow[p0 + 1]  = s1x * (1.0f / 9.0f);
    orow[p0 + 32] = s0y * (1.0f / 9.0f);
    orow[p0 + 33] = s1y * (1.0f / 9.0f);
}

__global__ __launch_bounds__(NTHREADS)
void ordfilter_kernel(const float* __restrict__ inp, float* __restrict__ out) {
    // sc[j][cy][p] : j-th largest of the vertical 5-window at packed column p
    //   lane .x = image column x0 + p - 2
    //   lane .y = image column x0 + 32 + p - 2
    __shared__ ScTile sc;

    const int b   = blockIdx.z;
    const int x0  = blockIdx.x * TILE_W;
    const int y0  = blockIdx.y * TILE_H;
    const int tx  = threadIdx.x;           // 0..15
    const int ty  = threadIdx.y;           // 0..15
    const int tid = ty * TPX + tx;
    const float* __restrict__ img = inp + (size_t)b * H * W;

    // ---- Phase 1: packed vertical column sorts (statically unrolled tasks) ----
    #pragma unroll
    for (int k = 0; k < 5; k++) {
        const int task = tid + k * NTHREADS;
        if (k < 4 || task < NTASKS) {      // k<4 always in range (1024 < 1152)
            const int p  = task % NPACK;
            const int cy = task / NPACK;
            const int gxL = reflect(x0 + p - 2, W);
            const int gxR = reflect(x0 + 32 + p - 2, W);
            __half2 v[5];
            #pragma unroll
            for (int j = 0; j < 5; j++) {
                const int yy = reflect(y0 + cy - 2 + j, H);
                const float* row = img + (size_t)yy * W;
                v[j] = __floats2half2_rn(row[gxL], row[gxR]);
            }
            sort5D(v);
            #pragma unroll
            for (int j = 0; j < 5; j++) sc[j][cy][p] = v[j];
        }
    }
    __syncthreads();

    // ---- Phase 2: two independent units per thread (rows ty and ty+16) ----
    float* orowA = out + ((size_t)b * H + (y0 + ty)) * W + x0;
    float* orowB = out + ((size_t)b * H + (y0 + ty + TYB)) * W + x0;
    phase2_unit(sc, ty,       tx, orowA);
    phase2_unit(sc, ty + TYB, tx, orowB);
}

} // namespace

extern "C" void kernel_launch(void* const* d_in, const int* in_sizes, int n_in,
                              void* d_out, int out_size) {
    const float* inp = (const float*)d_in[0];
    float* out = (float*)d_out;
    dim3 grid(W / TILE_W, H / TILE_H, B);   // 8 x 16 x 16 = 2048
    dim3 block(TPX, TYB);                   // 16 x 16
    ordfilter_kernel<<<grid, block>>>(inp, out);
}

// round 11
// speedup vs baseline: 2.2334x; 1.0816x over previous
#include <cuda_runtime.h>
#include <cuda_fp16.h>
#include <cuda_bf16.h>

namespace {

constexpr int B = 16, H = 512, W = 512;
constexpr int TPX    = 16;             // threads in x; each handles packed pixels 2tx, 2tx+1
constexpr int TYB    = 16;             // threads in y
constexpr int TILE_W = 64;             // tile width in pixels (halves packed 32 apart)
constexpr int TILE_H = 32;             // tile height: each thread does rows ty and ty+16
constexpr int NPACK  = 36;             // packed columns incl. halo (32 + 4)
constexpr int NTHREADS = TPX * TYB;    // 256
constexpr int NTASKS = NPACK * TILE_H; // 1152 column-sort tasks per block

__device__ __forceinline__ int reflect(int i, int n) {
    if (i < 0) i = -i;
    if (i >= n) i = 2 * n - 2 - i;
    return i;
}

// packed descending compare-exchange on 2 independent lanes: a >= b per lane
__device__ __forceinline__ void ceD(__half2& a, __half2& b) {
    __half2 mx = __hmax2(a, b);
    __half2 mn = __hmin2(a, b);
    a = mx; b = mn;
}

// greatest power of two strictly less than N (N >= 2)
template<int N> struct GP2    { static constexpr int value = 2 * GP2<(N + 1) / 2>::value; };
template<>      struct GP2<2> { static constexpr int value = 1; };
template<>      struct GP2<1> { static constexpr int value = 1; };

// Lang's arbitrary-N bitonic merge, descending output. Input bitonic (mountain).
template<int N>
__device__ __forceinline__ void bmergeD(__half2* v) {
    if constexpr (N > 1) {
        constexpr int K = GP2<N>::value;
        #pragma unroll
        for (int i = 0; i < N - K; i++) ceD(v[i], v[i + K]);
        bmergeD<K>(v);
        bmergeD<N - K>(v + K);
    }
}

// optimal 9-CE sorting network for 5 elements (descending), packed
__device__ __forceinline__ void sort5D(__half2* a) {
    ceD(a[0], a[1]); ceD(a[3], a[4]); ceD(a[2], a[4]); ceD(a[2], a[3]);
    ceD(a[1], a[4]); ceD(a[0], a[3]); ceD(a[0], a[2]); ceD(a[1], a[3]);
    ceD(a[1], a[2]);
}

// merge two sorted-desc-5 lists into sorted-desc-10 (15 CE)
__device__ __forceinline__ void merge55(const __half2* a, const __half2* b, __half2* out10) {
    #pragma unroll
    for (int j = 0; j < 5; j++) out10[j] = a[4 - j];   // ascending
    #pragma unroll
    for (int j = 0; j < 5; j++) out10[5 + j] = b[j];   // descending
    bmergeD<10>(out10);
}

// Algebraic final merge: sum of top-9 of (sorted-desc-9 u[0..8]) ∪ (sorted-desc-5 c).
// Bitonic split of asc(u)++desc(c): top-8 = {u0,u1,u2, max(u7-i,ci)}, 9th = max of
// the bitonic remainder {u8, min(u7-i,ci)}. Exact selection; fp32 sum.
// (sux, suy) = precomputed u0+u1+u2 per packed lane.
__device__ __forceinline__ float2 top9_sum(const __half2* u, const __half2* c,
                                           float sux, float suy) {
    __half2 mx0 = __hmax2(u[7], c[0]), mn0 = __hmin2(u[7], c[0]);
    __half2 mx1 = __hmax2(u[6], c[1]), mn1 = __hmin2(u[6], c[1]);
    __half2 mx2 = __hmax2(u[5], c[2]), mn2 = __hmin2(u[5], c[2]);
    __half2 mx3 = __hmax2(u[4], c[3]), mn3 = __hmin2(u[4], c[3]);
    __half2 mx4 = __hmax2(u[3], c[4]), mn4 = __hmin2(u[3], c[4]);
    // 9th largest = max of the 6 remaining (bitonic) values
    __half2 m9 = __hmax2(__hmax2(__hmax2(u[8], mn0), __hmax2(mn1, mn2)),
                         __hmax2(mn3, mn4));
    const float2 f0 = __half22float2(mx0);
    const float2 f1 = __half22float2(mx1);
    const float2 f2 = __half22float2(mx2);
    const float2 f3 = __half22float2(mx3);
    const float2 f4 = __half22float2(mx4);
    const float2 f9 = __half22float2(m9);
    float sx = sux + f0.x + f1.x + f2.x + f3.x + f4.x + f9.x;
    float sy = suy + f0.y + f1.y + f2.y + f3.y + f4.y + f9.y;
    return make_float2(sx, sy);
}

using ScTile = __half2[5][TILE_H][NPACK];

// One pixel-pair-unit: two adjacent packed pixels (4 real pixels) at tile row cy.
__device__ __forceinline__ void phase2_unit(const ScTile& sc, int cy, int tx,
                                            float* __restrict__ orow) {
    const int p0 = 2 * tx;

    // load 6 sorted columns as LDS.64 pairs (p0 even -> 8B aligned)
    __half2 col[6][5];
    #pragma unroll
    for (int j = 0; j < 5; j++) {
        #pragma unroll
        for (int c = 0; c < 6; c += 2) {
            const float2 r = *reinterpret_cast<const float2*>(&sc[j][cy][p0 + c]);
            col[c][j]     = *reinterpret_cast<const __half2*>(&r.x);
            col[c + 1][j] = *reinterpret_cast<const __half2*>(&r.y);
        }
    }

    // shared top-9 (sorted) of the 4 middle columns
    __half2 A10[10], B10[10];
    merge55(col[1], col[2], A10);
    merge55(col[3], col[4], B10);

    __half2 u[20];
    #pragma unroll
    for (int j = 0; j < 10; j++) u[j] = A10[9 - j];    // ascending
    #pragma unroll
    for (int j = 0; j < 10; j++) u[10 + j] = B10[j];   // descending
    bmergeD<20>(u);                                    // only u[0..8] used -> rest DCE'd

    // shared partial sum u0+u1+u2 (always in the top-9 of either pixel)
    const float2 g0 = __half22float2(u[0]);
    const float2 g1 = __half22float2(u[1]);
    const float2 g2 = __half22float2(u[2]);
    const float sux = g0.x + g1.x + g2.x;
    const float suy = g0.y + g1.y + g2.y;

    // per-pixel algebraic final merges with the private edge columns
    const float2 s0 = top9_sum(u, col[0], sux, suy);
    const float2 s1 = top9_sum(u, col[5], sux, suy);

    orow[p0]      = s0.x * (1.0f / 9.0f);
    orow[p0 + 1]  = s1.x * (1.0f / 9.0f);
    orow[p0 + 32] = s0.y * (1.0f / 9.0f);
    orow[p0 + 33] = s1.y * (1.0f / 9.0f);
}

__global__ __launch_bounds__(NTHREADS)
void ordfilter_kernel(const float* __restrict__ inp, float* __restrict__ out) {
    // sc[j][cy][p] : j-th largest of the vertical 5-window at packed column p
    //   lane .x = image column x0 + p - 2
    //   lane .y = image column x0 + 32 + p - 2
    __shared__ ScTile sc;

    const int b   = blockIdx.z;
    const int x0  = blockIdx.x * TILE_W;
    const int y0  = blockIdx.y * TILE_H;
    const int tx  = threadIdx.x;           // 0..15
    const int ty  = threadIdx.y;           // 0..15
    const int tid = ty * TPX + tx;
    const float* __restrict__ img = inp + (size_t)b * H * W;

    // ---- Phase 1: packed vertical column sorts (statically unrolled tasks) ----
    #pragma unroll
    for (int k = 0; k < 5; k++) {
        const int task = tid + k * NTHREADS;
        if (k < 4 || task < NTASKS) {      // k<4 always in range (1024 < 1152)
            const int p  = task % NPACK;
            const int cy = task / NPACK;
            const int gxL = reflect(x0 + p - 2, W);
            const int gxR = reflect(x0 + 32 + p - 2, W);
            __half2 v[5];
            #pragma unroll
            for (int j = 0; j < 5; j++) {
                const int yy = reflect(y0 + cy - 2 + j, H);
                const float* row = img + (size_t)yy * W;
                v[j] = __floats2half2_rn(row[gxL], row[gxR]);
            }
            sort5D(v);
            #pragma unroll
            for (int j = 0; j < 5; j++) sc[j][cy][p] = v[j];
        }
    }
    __syncthreads();

    // ---- Phase 2: two independent units per thread (rows ty and ty+16) ----
    float* orowA = out + ((size_t)b * H + (y0 + ty)) * W + x0;
    float* orowB = out + ((size_t)b * H + (y0 + ty + TYB)) * W + x0;
    phase2_unit(sc, ty,       tx, orowA);
    phase2_unit(sc, ty + TYB, tx, orowB);
}

} // namespace

extern "C" void kernel_launch(void* const* d_in, const int* in_sizes, int n_in,
                              void* d_out, int out_size) {
    const float* inp = (const float*)d_in[0];
    float* out = (float*)d_out;
    dim3 grid(W / TILE_W, H / TILE_H, B);   // 8 x 16 x 16 = 2048
    dim3 block(TPX, TYB);                   // 16 x 16
    ordfilter_kernel<<<grid, block>>>(inp, out);
}